// round 6
// baseline (speedup 1.0000x reference)
#include <cuda_runtime.h>
#include <cuda_bf16.h>
#include <math.h>
#include <stdint.h>

#define N_NODES 8192
#define DIN     512
#define DOUT    256
#define MAXN    512

// ---------------------------------------------------------------------------
// Device scratch (globals: allocation-free per harness rules)
// ---------------------------------------------------------------------------
__device__ float g_h[(size_t)N_NODES * DOUT];   // 8 MB
__device__ float g_g1[N_NODES];
__device__ float g_g2[N_NODES];
__device__ __align__(16) __nv_bfloat16 g_ahi[(size_t)N_NODES * DIN];  // 8 MB
__device__ __align__(16) __nv_bfloat16 g_alo[(size_t)N_NODES * DIN];  // 8 MB
__device__ __align__(16) __nv_bfloat16 g_whi[(size_t)DOUT * DIN];     // W^T [n][k]
__device__ __align__(16) __nv_bfloat16 g_wlo[(size_t)DOUT * DIN];

// ---------------------------------------------------------------------------
// PTX helpers
// ---------------------------------------------------------------------------
__device__ __forceinline__ uint32_t smem_u32(const void* p) {
    uint32_t a;
    asm("{ .reg .u64 t; cvta.to.shared.u64 t, %1; cvt.u32.u64 %0, t; }"
        : "=r"(a) : "l"(p));
    return a;
}
__device__ __forceinline__ void cp16(uint32_t dst, const void* src) {
    asm volatile("cp.async.ca.shared.global [%0], [%1], 16;"
                 :: "r"(dst), "l"(src) : "memory");
}
#define CP_COMMIT() asm volatile("cp.async.commit_group;" ::: "memory")
#define CP_WAIT(n)  asm volatile("cp.async.wait_group %0;" :: "n"(n) : "memory")

__device__ __forceinline__ uint32_t lds32(uint32_t addr) {
    uint32_t v;
    asm volatile("ld.shared.b32 %0, [%1];" : "=r"(v) : "r"(addr));
    return v;
}
__device__ __forceinline__ void mma16816(float* d, const uint32_t* a,
                                         const uint32_t* b) {
    asm volatile(
        "mma.sync.aligned.m16n8k16.row.col.f32.bf16.bf16.f32 "
        "{%0,%1,%2,%3}, {%4,%5,%6,%7}, {%8,%9}, {%0,%1,%2,%3};"
        : "+f"(d[0]), "+f"(d[1]), "+f"(d[2]), "+f"(d[3])
        : "r"(a[0]), "r"(a[1]), "r"(a[2]), "r"(a[3]), "r"(b[0]), "r"(b[1]));
}
__device__ __forceinline__ unsigned short bf16b(float v) {
    __nv_bfloat16 h = __float2bfloat16_rn(v);
    return *reinterpret_cast<unsigned short*>(&h);
}
__device__ __forceinline__ float4 ldcs4(const float4* p) {
    float4 v;
    asm volatile("ld.global.cs.v4.f32 {%0,%1,%2,%3}, [%4];"
                 : "=f"(v.x), "=f"(v.y), "=f"(v.z), "=f"(v.w) : "l"(p));
    return v;
}

// ---------------------------------------------------------------------------
// Prep A: elu(x) -> bf16 hi/lo, row-major [8192][512].
// ---------------------------------------------------------------------------
__global__ void __launch_bounds__(256)
prep_a_kernel(const float* __restrict__ X)
{
    int T = blockIdx.x * 256 + threadIdx.x;     // 0 .. 524287
    int m  = T >> 6;
    int k0 = (T & 63) << 3;

    float4 v0 = *(const float4*)(X + (size_t)m * DIN + k0);
    float4 v1 = *(const float4*)(X + (size_t)m * DIN + k0 + 4);
    float f[8] = {v0.x, v0.y, v0.z, v0.w, v1.x, v1.y, v1.z, v1.w};

    unsigned short hs[8], ls[8];
#pragma unroll
    for (int i = 0; i < 8; i++) {
        float v = f[i] > 0.f ? f[i] : expm1f(f[i]);
        hs[i] = bf16b(v);
        float hf = __uint_as_float((uint32_t)hs[i] << 16);
        ls[i] = bf16b(v - hf);
    }
    uint4 ph, pl;
    ph.x = hs[0] | ((uint32_t)hs[1] << 16); ph.y = hs[2] | ((uint32_t)hs[3] << 16);
    ph.z = hs[4] | ((uint32_t)hs[5] << 16); ph.w = hs[6] | ((uint32_t)hs[7] << 16);
    pl.x = ls[0] | ((uint32_t)ls[1] << 16); pl.y = ls[2] | ((uint32_t)ls[3] << 16);
    pl.z = ls[4] | ((uint32_t)ls[5] << 16); pl.w = ls[6] | ((uint32_t)ls[7] << 16);

    *(uint4*)(g_ahi + (size_t)m * DIN + k0) = ph;
    *(uint4*)(g_alo + (size_t)m * DIN + k0) = pl;
}

// ---------------------------------------------------------------------------
// Prep W: W[512,256] -> W^T hi/lo bf16 [256 n][512 k].
// ---------------------------------------------------------------------------
__global__ void __launch_bounds__(256)
prep_w_kernel(const float* __restrict__ W)
{
    int T = blockIdx.x * 256 + threadIdx.x;     // 0..16383
    int n  = T >> 6;
    int k0 = (T & 63) << 3;

    unsigned short hs[8], ls[8];
#pragma unroll
    for (int i = 0; i < 8; i++) {
        float v = W[(size_t)(k0 + i) * DOUT + n];
        hs[i] = bf16b(v);
        float hf = __uint_as_float((uint32_t)hs[i] << 16);
        ls[i] = bf16b(v - hf);
    }
    uint4 ph, pl;
    ph.x = hs[0] | ((uint32_t)hs[1] << 16); ph.y = hs[2] | ((uint32_t)hs[3] << 16);
    ph.z = hs[4] | ((uint32_t)hs[5] << 16); ph.w = hs[6] | ((uint32_t)hs[7] << 16);
    pl.x = ls[0] | ((uint32_t)ls[1] << 16); pl.y = ls[2] | ((uint32_t)ls[3] << 16);
    pl.z = ls[4] | ((uint32_t)ls[5] << 16); pl.w = ls[6] | ((uint32_t)ls[7] << 16);

    *(uint4*)(g_whi + (size_t)n * DIN + k0) = ph;
    *(uint4*)(g_wlo + (size_t)n * DIN + k0) = pl;
}

// ---------------------------------------------------------------------------
// mma.sync GEMM: h = A@W^T + b with 3-term bf16 split.  (unchanged from R5)
// ---------------------------------------------------------------------------
#define SA 40
#define STG 10240
#define N_STAGES 48

__global__ void __launch_bounds__(256)
gemm_mma_kernel(const float* __restrict__ b)
{
    __shared__ __align__(16) unsigned char sm[4 * STG];

    const int t    = threadIdx.x;
    const int wid  = t >> 5;
    const int lane = t & 31;
    const int g    = lane >> 2;
    const int tl   = lane & 3;
    const int wm0  = (wid >> 2) * 64;
    const int wn0  = (wid & 3) * 32;
    const int m0   = blockIdx.y * 128;
    const int n0   = blockIdx.x * 128;

    const uint32_t sbase = smem_u32(sm);

    float d[4][4][4];
#pragma unroll
    for (int mt = 0; mt < 4; mt++)
#pragma unroll
        for (int nt = 0; nt < 4; nt++)
#pragma unroll
            for (int i = 0; i < 4; i++) d[mt][nt][i] = 0.f;

    const int crow0 = t >> 2;
    const int crow1 = crow0 + 64;
    const int cc    = (t & 3) << 3;

    auto load_stage = [&](int s) {
        const int term = s >> 4;
        const int kt   = (s & 15) << 5;
        const __nv_bfloat16* aS = (term == 1) ? g_alo : g_ahi;
        const __nv_bfloat16* bS = (term == 2) ? g_wlo : g_whi;
        const int buf = s & 1;
        uint32_t aBase = sbase + buf * STG;
        uint32_t bBase = sbase + 2 * STG + buf * STG;
        cp16(aBase + crow0 * (SA * 2) + cc * 2,
             aS + (size_t)(m0 + crow0) * DIN + kt + cc);
        cp16(aBase + crow1 * (SA * 2) + cc * 2,
             aS + (size_t)(m0 + crow1) * DIN + kt + cc);
        cp16(bBase + crow0 * (SA * 2) + cc * 2,
             bS + (size_t)(n0 + crow0) * DIN + kt + cc);
        cp16(bBase + crow1 * (SA * 2) + cc * 2,
             bS + (size_t)(n0 + crow1) * DIN + kt + cc);
    };

    load_stage(0);
    CP_COMMIT();

    for (int s = 0; s < N_STAGES; s++) {
        if (s + 1 < N_STAGES) {
            load_stage(s + 1);
            CP_COMMIT();
            CP_WAIT(1);
        } else {
            CP_WAIT(0);
        }
        __syncthreads();

        const int buf = s & 1;
        const uint32_t aT = sbase + buf * STG + (wm0 + g) * (SA * 2) + tl * 4;
        const uint32_t bT = sbase + 2 * STG + buf * STG + (wn0 + g) * (SA * 2) + tl * 4;

#pragma unroll
        for (int kh = 0; kh < 2; kh++) {
            const uint32_t ko = kh * 32;
            uint32_t a[4][4], bb[4][2];
#pragma unroll
            for (int mt = 0; mt < 4; mt++) {
                uint32_t r = aT + mt * (16 * SA * 2) + ko;
                a[mt][0] = lds32(r);
                a[mt][1] = lds32(r + 8 * SA * 2);
                a[mt][2] = lds32(r + 16);
                a[mt][3] = lds32(r + 8 * SA * 2 + 16);
            }
#pragma unroll
            for (int nt = 0; nt < 4; nt++) {
                uint32_t r = bT + nt * (8 * SA * 2) + ko;
                bb[nt][0] = lds32(r);
                bb[nt][1] = lds32(r + 16);
            }
#pragma unroll
            for (int mt = 0; mt < 4; mt++)
#pragma unroll
                for (int nt = 0; nt < 4; nt++)
                    mma16816(d[mt][nt], a[mt], bb[nt]);
        }
        __syncthreads();
    }

    float2 bias[4];
#pragma unroll
    for (int nt = 0; nt < 4; nt++)
        bias[nt] = *(const float2*)(b + n0 + wn0 + nt * 8 + 2 * tl);

#pragma unroll
    for (int mt = 0; mt < 4; mt++) {
        int row0 = m0 + wm0 + mt * 16 + g;
#pragma unroll
        for (int nt = 0; nt < 4; nt++) {
            int col = n0 + wn0 + nt * 8 + 2 * tl;
            float2 v0 = make_float2(d[mt][nt][0] + bias[nt].x,
                                    d[mt][nt][1] + bias[nt].y);
            float2 v1 = make_float2(d[mt][nt][2] + bias[nt].x,
                                    d[mt][nt][3] + bias[nt].y);
            *(float2*)(g_h + (size_t)row0 * DOUT + col) = v0;
            *(float2*)(g_h + (size_t)(row0 + 8) * DOUT + col) = v1;
        }
    }
}

// ---------------------------------------------------------------------------
// Kernel G (vectorized): g1[i] = h[i]·a1_w + a1_b ; g2[i] = h[i]·a2_w + a2_b
// One warp per row; lane covers float4 c=lane and c=lane+32.
// ---------------------------------------------------------------------------
__global__ void g_kernel(const float* __restrict__ a1w, const float* __restrict__ a1b,
                         const float* __restrict__ a2w, const float* __restrict__ a2b)
{
    int warp = threadIdx.x >> 5;
    int lane = threadIdx.x & 31;
    int r = blockIdx.x * 8 + warp;
    const float4* hr = (const float4*)(g_h + (size_t)r * DOUT);
    const float4* w1 = (const float4*)a1w;
    const float4* w2 = (const float4*)a2w;

    float4 h0 = hr[lane];
    float4 h1 = hr[lane + 32];
    float4 u0 = w1[lane], u1 = w1[lane + 32];
    float4 v0 = w2[lane], v1 = w2[lane + 32];

    float s1 = h0.x * u0.x + h0.y * u0.y + h0.z * u0.z + h0.w * u0.w
             + h1.x * u1.x + h1.y * u1.y + h1.z * u1.z + h1.w * u1.w;
    float s2 = h0.x * v0.x + h0.y * v0.y + h0.z * v0.z + h0.w * v0.w
             + h1.x * v1.x + h1.y * v1.y + h1.z * v1.z + h1.w * v1.w;
#pragma unroll
    for (int o = 16; o; o >>= 1) {
        s1 += __shfl_xor_sync(0xffffffffu, s1, o);
        s2 += __shfl_xor_sync(0xffffffffu, s2, o);
    }
    if (lane == 0) {
        g_g1[r] = s1 + a1b[0];
        g_g2[r] = s2 + a2b[0];
    }
}

// ---------------------------------------------------------------------------
// attn kernel: per-row adjacency scan (MLP-8 streaming loads) + masked softmax
// + weighted aggregation.
// ---------------------------------------------------------------------------
__global__ void __launch_bounds__(256)
attn_kernel(const float* __restrict__ adj, float* __restrict__ out)
{
    __shared__ int   s_idx[MAXN];
    __shared__ float s_e[MAXN];
    __shared__ int   s_cnt;
    __shared__ float s_inv;

    const int i = blockIdx.x;
    const int t = threadIdx.x;

    if (t == 0) s_cnt = 0;
    __syncthreads();

    const float g2i = g_g2[i];
    const float4* row = (const float4*)(adj + (size_t)i * N_NODES);

    // batched streaming loads: full MLP, evict-first (keep g_h in L2)
    float4 v[8];
#pragma unroll
    for (int u = 0; u < 8; u++) v[u] = ldcs4(row + t + u * 256);

#pragma unroll
    for (int u = 0; u < 8; u++) {
        int jb = (t + u * 256) << 2;
        if (v[u].x > 0.f) { int p = atomicAdd(&s_cnt, 1); if (p < MAXN) { float s = g2i + g_g1[jb + 0]; s_idx[p] = jb + 0; s_e[p] = s > 0.f ? s : 0.2f * s; } }
        if (v[u].y > 0.f) { int p = atomicAdd(&s_cnt, 1); if (p < MAXN) { float s = g2i + g_g1[jb + 1]; s_idx[p] = jb + 1; s_e[p] = s > 0.f ? s : 0.2f * s; } }
        if (v[u].z > 0.f) { int p = atomicAdd(&s_cnt, 1); if (p < MAXN) { float s = g2i + g_g1[jb + 2]; s_idx[p] = jb + 2; s_e[p] = s > 0.f ? s : 0.2f * s; } }
        if (v[u].w > 0.f) { int p = atomicAdd(&s_cnt, 1); if (p < MAXN) { float s = g2i + g_g1[jb + 3]; s_idx[p] = jb + 3; s_e[p] = s > 0.f ? s : 0.2f * s; } }
    }
    __syncthreads();

    const int cnt = s_cnt < MAXN ? s_cnt : MAXN;

    if (cnt == 0) {
        float acc = 0.f;
        for (int r = 0; r < N_NODES; r++) acc += g_h[(size_t)r * DOUT + t];
        out[(size_t)i * DOUT + t] = acc * (1.f / (float)N_NODES);
        return;
    }

    if (t < 32) {
        float m = -INFINITY;
        for (int k = t; k < cnt; k += 32) m = fmaxf(m, s_e[k]);
#pragma unroll
        for (int o = 16; o; o >>= 1) m = fmaxf(m, __shfl_xor_sync(0xffffffffu, m, o));
        float ssum = 0.f;
        for (int k = t; k < cnt; k += 32) {
            float w = __expf(s_e[k] - m);
            s_e[k] = w;
            ssum += w;
        }
#pragma unroll
        for (int o = 16; o; o >>= 1) ssum += __shfl_xor_sync(0xffffffffu, ssum, o);
        if (t == 0) s_inv = 1.f / ssum;
    }
    __syncthreads();

    const float inv = s_inv;
    float a0 = 0.f, a1 = 0.f, a2 = 0.f, a3 = 0.f;
    int k = 0;
    for (; k + 4 <= cnt; k += 4) {
        a0 = fmaf(s_e[k + 0], g_h[(size_t)s_idx[k + 0] * DOUT + t], a0);
        a1 = fmaf(s_e[k + 1], g_h[(size_t)s_idx[k + 1] * DOUT + t], a1);
        a2 = fmaf(s_e[k + 2], g_h[(size_t)s_idx[k + 2] * DOUT + t], a2);
        a3 = fmaf(s_e[k + 3], g_h[(size_t)s_idx[k + 3] * DOUT + t], a3);
    }
    for (; k < cnt; k++)
        a0 = fmaf(s_e[k], g_h[(size_t)s_idx[k] * DOUT + t], a0);

    out[(size_t)i * DOUT + t] = (a0 + a1 + a2 + a3) * inv;
}

// ---------------------------------------------------------------------------
extern "C" void kernel_launch(void* const* d_in, const int* in_sizes, int n_in,
                              void* d_out, int out_size)
{
    const float* x   = (const float*)d_in[0];   // [8192, 512]
    const float* adj = (const float*)d_in[1];   // [8192, 8192]
    const float* W1  = (const float*)d_in[2];   // [512, 256]
    const float* b1  = (const float*)d_in[3];   // [256]
    const float* a1w = (const float*)d_in[4];   // [256]
    const float* a1b = (const float*)d_in[5];   // scalar
    const float* a2w = (const float*)d_in[6];   // [256]
    const float* a2b = (const float*)d_in[7];   // scalar
    float* out = (float*)d_out;                 // [8192, 256]

    prep_a_kernel<<<2048, 256>>>(x);
    prep_w_kernel<<<64, 256>>>(W1);
    dim3 gg(DOUT / 128, N_NODES / 128);         // (2, 64)
    gemm_mma_kernel<<<gg, 256>>>(b1);
    g_kernel<<<N_NODES / 8, 256>>>(a1w, a1b, a2w, a2b);
    attn_kernel<<<N_NODES, 256>>>(adj, out);
}

// round 7
// speedup vs baseline: 1.1407x; 1.1407x over previous
#include <cuda_runtime.h>
#include <cuda_bf16.h>
#include <math.h>
#include <stdint.h>

#define N_NODES 8192
#define DIN     512
#define DOUT    256
#define MAXN    512

// ---------------------------------------------------------------------------
// Device scratch (globals: allocation-free per harness rules)
// ---------------------------------------------------------------------------
__device__ float g_h[(size_t)N_NODES * DOUT];   // 8 MB
__device__ float g_g1[N_NODES];
__device__ float g_g2[N_NODES];
__device__ __align__(16) __nv_bfloat16 g_ahi[(size_t)N_NODES * DIN];  // 8 MB
__device__ __align__(16) __nv_bfloat16 g_alo[(size_t)N_NODES * DIN];  // 8 MB
__device__ __align__(16) __nv_bfloat16 g_whi[(size_t)DOUT * DIN];     // W^T [n][k]
__device__ __align__(16) __nv_bfloat16 g_wlo[(size_t)DOUT * DIN];

// ---------------------------------------------------------------------------
// PTX helpers
// ---------------------------------------------------------------------------
__device__ __forceinline__ uint32_t smem_u32(const void* p) {
    uint32_t a;
    asm("{ .reg .u64 t; cvta.to.shared.u64 t, %1; cvt.u32.u64 %0, t; }"
        : "=r"(a) : "l"(p));
    return a;
}
__device__ __forceinline__ void cp16(uint32_t dst, const void* src) {
    asm volatile("cp.async.ca.shared.global [%0], [%1], 16;"
                 :: "r"(dst), "l"(src) : "memory");
}
#define CP_COMMIT() asm volatile("cp.async.commit_group;" ::: "memory")
#define CP_WAIT(n)  asm volatile("cp.async.wait_group %0;" :: "n"(n) : "memory")

__device__ __forceinline__ uint32_t lds32(uint32_t addr) {
    uint32_t v;
    asm volatile("ld.shared.b32 %0, [%1];" : "=r"(v) : "r"(addr));
    return v;
}
__device__ __forceinline__ void mma16816(float* d, const uint32_t* a,
                                         const uint32_t* b) {
    asm volatile(
        "mma.sync.aligned.m16n8k16.row.col.f32.bf16.bf16.f32 "
        "{%0,%1,%2,%3}, {%4,%5,%6,%7}, {%8,%9}, {%0,%1,%2,%3};"
        : "+f"(d[0]), "+f"(d[1]), "+f"(d[2]), "+f"(d[3])
        : "r"(a[0]), "r"(a[1]), "r"(a[2]), "r"(a[3]), "r"(b[0]), "r"(b[1]));
}
__device__ __forceinline__ unsigned short bf16b(float v) {
    __nv_bfloat16 h = __float2bfloat16_rn(v);
    return *reinterpret_cast<unsigned short*>(&h);
}

// ---------------------------------------------------------------------------
// Prep A: elu(x) -> bf16 hi/lo, row-major [8192][512].
// ---------------------------------------------------------------------------
__global__ void __launch_bounds__(256)
prep_a_kernel(const float* __restrict__ X)
{
    int T = blockIdx.x * 256 + threadIdx.x;     // 0 .. 524287
    int m  = T >> 6;
    int k0 = (T & 63) << 3;

    float4 v0 = *(const float4*)(X + (size_t)m * DIN + k0);
    float4 v1 = *(const float4*)(X + (size_t)m * DIN + k0 + 4);
    float f[8] = {v0.x, v0.y, v0.z, v0.w, v1.x, v1.y, v1.z, v1.w};

    unsigned short hs[8], ls[8];
#pragma unroll
    for (int i = 0; i < 8; i++) {
        float v = f[i] > 0.f ? f[i] : expm1f(f[i]);
        hs[i] = bf16b(v);
        float hf = __uint_as_float((uint32_t)hs[i] << 16);
        ls[i] = bf16b(v - hf);
    }
    uint4 ph, pl;
    ph.x = hs[0] | ((uint32_t)hs[1] << 16); ph.y = hs[2] | ((uint32_t)hs[3] << 16);
    ph.z = hs[4] | ((uint32_t)hs[5] << 16); ph.w = hs[6] | ((uint32_t)hs[7] << 16);
    pl.x = ls[0] | ((uint32_t)ls[1] << 16); pl.y = ls[2] | ((uint32_t)ls[3] << 16);
    pl.z = ls[4] | ((uint32_t)ls[5] << 16); pl.w = ls[6] | ((uint32_t)ls[7] << 16);

    *(uint4*)(g_ahi + (size_t)m * DIN + k0) = ph;
    *(uint4*)(g_alo + (size_t)m * DIN + k0) = pl;
}

// ---------------------------------------------------------------------------
// Prep W: W[512,256] -> W^T hi/lo bf16 [256 n][512 k].
// Also initializes g_g1/g_g2 to the biases (gemm epilogue accumulates into them).
// ---------------------------------------------------------------------------
__global__ void __launch_bounds__(256)
prep_w_kernel(const float* __restrict__ W,
              const float* __restrict__ a1b, const float* __restrict__ a2b)
{
    int T = blockIdx.x * 256 + threadIdx.x;     // 0..16383
    if (T < N_NODES) {
        g_g1[T] = a1b[0];
        g_g2[T] = a2b[0];
    }
    int n  = T >> 6;
    int k0 = (T & 63) << 3;

    unsigned short hs[8], ls[8];
#pragma unroll
    for (int i = 0; i < 8; i++) {
        float v = W[(size_t)(k0 + i) * DOUT + n];
        hs[i] = bf16b(v);
        float hf = __uint_as_float((uint32_t)hs[i] << 16);
        ls[i] = bf16b(v - hf);
    }
    uint4 ph, pl;
    ph.x = hs[0] | ((uint32_t)hs[1] << 16); ph.y = hs[2] | ((uint32_t)hs[3] << 16);
    ph.z = hs[4] | ((uint32_t)hs[5] << 16); ph.w = hs[6] | ((uint32_t)hs[7] << 16);
    pl.x = ls[0] | ((uint32_t)ls[1] << 16); pl.y = ls[2] | ((uint32_t)ls[3] << 16);
    pl.z = ls[4] | ((uint32_t)ls[5] << 16); pl.w = ls[6] | ((uint32_t)ls[7] << 16);

    *(uint4*)(g_whi + (size_t)n * DIN + k0) = ph;
    *(uint4*)(g_wlo + (size_t)n * DIN + k0) = pl;
}

// ---------------------------------------------------------------------------
// mma.sync GEMM: h = A@W^T + b with 3-term bf16 split.
// Epilogue also accumulates g1/g2 row scores via spread atomics.
// ---------------------------------------------------------------------------
#define SA 40
#define STG 10240
#define N_STAGES 48

__global__ void __launch_bounds__(256)
gemm_mma_kernel(const float* __restrict__ b,
                const float* __restrict__ a1w, const float* __restrict__ a2w)
{
    __shared__ __align__(16) unsigned char sm[4 * STG];

    const int t    = threadIdx.x;
    const int wid  = t >> 5;
    const int lane = t & 31;
    const int g    = lane >> 2;
    const int tl   = lane & 3;
    const int wm0  = (wid >> 2) * 64;
    const int wn0  = (wid & 3) * 32;
    const int m0   = blockIdx.y * 128;
    const int n0   = blockIdx.x * 128;

    const uint32_t sbase = smem_u32(sm);

    float d[4][4][4];
#pragma unroll
    for (int mt = 0; mt < 4; mt++)
#pragma unroll
        for (int nt = 0; nt < 4; nt++)
#pragma unroll
            for (int i = 0; i < 4; i++) d[mt][nt][i] = 0.f;

    const int crow0 = t >> 2;
    const int crow1 = crow0 + 64;
    const int cc    = (t & 3) << 3;

    auto load_stage = [&](int s) {
        const int term = s >> 4;
        const int kt   = (s & 15) << 5;
        const __nv_bfloat16* aS = (term == 1) ? g_alo : g_ahi;
        const __nv_bfloat16* bS = (term == 2) ? g_wlo : g_whi;
        const int buf = s & 1;
        uint32_t aBase = sbase + buf * STG;
        uint32_t bBase = sbase + 2 * STG + buf * STG;
        cp16(aBase + crow0 * (SA * 2) + cc * 2,
             aS + (size_t)(m0 + crow0) * DIN + kt + cc);
        cp16(aBase + crow1 * (SA * 2) + cc * 2,
             aS + (size_t)(m0 + crow1) * DIN + kt + cc);
        cp16(bBase + crow0 * (SA * 2) + cc * 2,
             bS + (size_t)(n0 + crow0) * DIN + kt + cc);
        cp16(bBase + crow1 * (SA * 2) + cc * 2,
             bS + (size_t)(n0 + crow1) * DIN + kt + cc);
    };

    load_stage(0);
    CP_COMMIT();

    for (int s = 0; s < N_STAGES; s++) {
        if (s + 1 < N_STAGES) {
            load_stage(s + 1);
            CP_COMMIT();
            CP_WAIT(1);
        } else {
            CP_WAIT(0);
        }
        __syncthreads();

        const int buf = s & 1;
        const uint32_t aT = sbase + buf * STG + (wm0 + g) * (SA * 2) + tl * 4;
        const uint32_t bT = sbase + 2 * STG + buf * STG + (wn0 + g) * (SA * 2) + tl * 4;

#pragma unroll
        for (int kh = 0; kh < 2; kh++) {
            const uint32_t ko = kh * 32;
            uint32_t a[4][4], bb[4][2];
#pragma unroll
            for (int mt = 0; mt < 4; mt++) {
                uint32_t r = aT + mt * (16 * SA * 2) + ko;
                a[mt][0] = lds32(r);
                a[mt][1] = lds32(r + 8 * SA * 2);
                a[mt][2] = lds32(r + 16);
                a[mt][3] = lds32(r + 8 * SA * 2 + 16);
            }
#pragma unroll
            for (int nt = 0; nt < 4; nt++) {
                uint32_t r = bT + nt * (8 * SA * 2) + ko;
                bb[nt][0] = lds32(r);
                bb[nt][1] = lds32(r + 16);
            }
#pragma unroll
            for (int mt = 0; mt < 4; mt++)
#pragma unroll
                for (int nt = 0; nt < 4; nt++)
                    mma16816(d[mt][nt], a[mt], bb[nt]);
        }
        __syncthreads();
    }

    // ---- epilogue: + bias, write h, accumulate g1/g2 ----
    float2 bias[4], w1c[4], w2c[4];
#pragma unroll
    for (int nt = 0; nt < 4; nt++) {
        int col = n0 + wn0 + nt * 8 + 2 * tl;
        bias[nt] = *(const float2*)(b + col);
        w1c[nt]  = *(const float2*)(a1w + col);
        w2c[nt]  = *(const float2*)(a2w + col);
    }

#pragma unroll
    for (int mt = 0; mt < 4; mt++) {
        int row0 = m0 + wm0 + mt * 16 + g;
        float s1r0 = 0.f, s2r0 = 0.f, s1r1 = 0.f, s2r1 = 0.f;
#pragma unroll
        for (int nt = 0; nt < 4; nt++) {
            int col = n0 + wn0 + nt * 8 + 2 * tl;
            float2 v0 = make_float2(d[mt][nt][0] + bias[nt].x,
                                    d[mt][nt][1] + bias[nt].y);
            float2 v1 = make_float2(d[mt][nt][2] + bias[nt].x,
                                    d[mt][nt][3] + bias[nt].y);
            *(float2*)(g_h + (size_t)row0 * DOUT + col) = v0;
            *(float2*)(g_h + (size_t)(row0 + 8) * DOUT + col) = v1;
            s1r0 = fmaf(v0.x, w1c[nt].x, fmaf(v0.y, w1c[nt].y, s1r0));
            s2r0 = fmaf(v0.x, w2c[nt].x, fmaf(v0.y, w2c[nt].y, s2r0));
            s1r1 = fmaf(v1.x, w1c[nt].x, fmaf(v1.y, w1c[nt].y, s1r1));
            s2r1 = fmaf(v1.x, w2c[nt].x, fmaf(v1.y, w2c[nt].y, s2r1));
        }
        atomicAdd(&g_g1[row0], s1r0);
        atomicAdd(&g_g2[row0], s2r0);
        atomicAdd(&g_g1[row0 + 8], s1r1);
        atomicAdd(&g_g2[row0 + 8], s2r1);
    }
}

// ---------------------------------------------------------------------------
// attn kernel: per-row adjacency scan + masked softmax + weighted aggregation.
// (R5 version, verbatim)
// ---------------------------------------------------------------------------
__global__ void __launch_bounds__(256)
attn_kernel(const float* __restrict__ adj, float* __restrict__ out)
{
    __shared__ int   s_idx[MAXN];
    __shared__ float s_e[MAXN];
    __shared__ int   s_cnt;
    __shared__ float s_inv;

    const int i = blockIdx.x;
    const int t = threadIdx.x;

    if (t == 0) s_cnt = 0;
    __syncthreads();

    const float g2i = g_g2[i];
    const float4* row = (const float4*)(adj + (size_t)i * N_NODES);

#pragma unroll
    for (int u = 0; u < 8; u++) {
        int f = t + u * 256;
        float4 v = row[f];
        int jb = f << 2;
        if (v.x > 0.f) { int p = atomicAdd(&s_cnt, 1); if (p < MAXN) { float s = g2i + g_g1[jb + 0]; s_idx[p] = jb + 0; s_e[p] = s > 0.f ? s : 0.2f * s; } }
        if (v.y > 0.f) { int p = atomicAdd(&s_cnt, 1); if (p < MAXN) { float s = g2i + g_g1[jb + 1]; s_idx[p] = jb + 1; s_e[p] = s > 0.f ? s : 0.2f * s; } }
        if (v.z > 0.f) { int p = atomicAdd(&s_cnt, 1); if (p < MAXN) { float s = g2i + g_g1[jb + 2]; s_idx[p] = jb + 2; s_e[p] = s > 0.f ? s : 0.2f * s; } }
        if (v.w > 0.f) { int p = atomicAdd(&s_cnt, 1); if (p < MAXN) { float s = g2i + g_g1[jb + 3]; s_idx[p] = jb + 3; s_e[p] = s > 0.f ? s : 0.2f * s; } }
    }
    __syncthreads();

    const int cnt = s_cnt < MAXN ? s_cnt : MAXN;

    if (cnt == 0) {
        float acc = 0.f;
        for (int r = 0; r < N_NODES; r++) acc += g_h[(size_t)r * DOUT + t];
        out[(size_t)i * DOUT + t] = acc * (1.f / (float)N_NODES);
        return;
    }

    if (t < 32) {
        float m = -INFINITY;
        for (int k = t; k < cnt; k += 32) m = fmaxf(m, s_e[k]);
#pragma unroll
        for (int o = 16; o; o >>= 1) m = fmaxf(m, __shfl_xor_sync(0xffffffffu, m, o));
        float ssum = 0.f;
        for (int k = t; k < cnt; k += 32) {
            float w = __expf(s_e[k] - m);
            s_e[k] = w;
            ssum += w;
        }
#pragma unroll
        for (int o = 16; o; o >>= 1) ssum += __shfl_xor_sync(0xffffffffu, ssum, o);
        if (t == 0) s_inv = 1.f / ssum;
    }
    __syncthreads();

    const float inv = s_inv;
    float a0 = 0.f, a1 = 0.f, a2 = 0.f, a3 = 0.f;
    int k = 0;
    for (; k + 4 <= cnt; k += 4) {
        a0 = fmaf(s_e[k + 0], g_h[(size_t)s_idx[k + 0] * DOUT + t], a0);
        a1 = fmaf(s_e[k + 1], g_h[(size_t)s_idx[k + 1] * DOUT + t], a1);
        a2 = fmaf(s_e[k + 2], g_h[(size_t)s_idx[k + 2] * DOUT + t], a2);
        a3 = fmaf(s_e[k + 3], g_h[(size_t)s_idx[k + 3] * DOUT + t], a3);
    }
    for (; k < cnt; k++)
        a0 = fmaf(s_e[k], g_h[(size_t)s_idx[k] * DOUT + t], a0);

    out[(size_t)i * DOUT + t] = (a0 + a1 + a2 + a3) * inv;
}

// ---------------------------------------------------------------------------
extern "C" void kernel_launch(void* const* d_in, const int* in_sizes, int n_in,
                              void* d_out, int out_size)
{
    const float* x   = (const float*)d_in[0];   // [8192, 512]
    const float* adj = (const float*)d_in[1];   // [8192, 8192]
    const float* W1  = (const float*)d_in[2];   // [512, 256]
    const float* b1  = (const float*)d_in[3];   // [256]
    const float* a1w = (const float*)d_in[4];   // [256]
    const float* a1b = (const float*)d_in[5];   // scalar
    const float* a2w = (const float*)d_in[6];   // [256]
    const float* a2b = (const float*)d_in[7];   // scalar
    float* out = (float*)d_out;                 // [8192, 256]

    prep_a_kernel<<<2048, 256>>>(x);
    prep_w_kernel<<<64, 256>>>(W1, a1b, a2b);
    dim3 gg(DOUT / 128, N_NODES / 128);         // (2, 64)
    gemm_mma_kernel<<<gg, 256>>>(b1, a1w, a2w);
    attn_kernel<<<N_NODES, 256>>>(adj, out);
}